// round 2
// baseline (speedup 1.0000x reference)
#include <cuda_runtime.h>
#include <cstdint>

// Problem constants (B=2, S=256, H=1024, V=131072, C=512, TOP_K=2)
#define NT   512      // B*S tokens
#define HD   1024     // hidden
#define NC   512      // centroids
#define NV   131072   // vocab
#define VPC  256      // vocab per centroid = NV/NC
#define TOPK 2

// ---- scratch (no allocations allowed) ----
__device__ int      g_top2[NT * TOPK];       // top-2 cluster ids per token
__device__ int      g_count[NC];             // tokens routed to each cluster
__device__ int      g_list[NC * NT];         // packed (token<<1)|k per cluster
__device__ float    g_sel[NT * TOPK * VPC];  // selected logits
__device__ unsigned g_minkey;                // order-preserving-encoded global min
__device__ int      g_inv[NV];               // inverse permutation of token_ordering

// order-preserving float<->uint mapping (monotone for unsigned compare)
__device__ __forceinline__ unsigned enc_f(float f) {
    unsigned u = __float_as_uint(f);
    return (u & 0x80000000u) ? ~u : (u | 0x80000000u);
}
__device__ __forceinline__ float dec_f(unsigned u) {
    return __uint_as_float((u & 0x80000000u) ? (u ^ 0x80000000u) : ~u);
}

// ---------------------------------------------------------------------------
// K0: zero counters, init min, build inverse permutation
// ---------------------------------------------------------------------------
__global__ void k_init(const int* __restrict__ ordering) {
    int i = blockIdx.x * blockDim.x + threadIdx.x;
    if (i < NC) g_count[i] = 0;
    if (i == 0) g_minkey = 0xFFFFFFFFu;
    if (i < NV) g_inv[ordering[i]] = i;
}

// ---------------------------------------------------------------------------
// K1: centroid routing + top-2 + build per-cluster token lists.
// 8 tokens per block (64 blocks x 256 threads). Each thread owns 2 centroids
// and accumulates 8 token dots simultaneously from smem hidden states.
// ---------------------------------------------------------------------------
__global__ void __launch_bounds__(256) k_route(const float* __restrict__ hs,
                                               const float* __restrict__ cw) {
    const int TT = 8;
    __shared__ float4 hsm[TT][HD / 4];  // 32 KB
    __shared__ float  lg[TT][NC];       // 16 KB  (total 48 KB static, at limit)
    int tid  = threadIdx.x;
    int t0   = blockIdx.x * TT;

    // load 8 hidden states
    for (int e = tid; e < TT * (HD / 4); e += 256) {
        int tt = e >> 8, j = e & 255;
        hsm[tt][j] = reinterpret_cast<const float4*>(hs)[(size_t)(t0 + tt) * (HD / 4) + j];
    }
    __syncthreads();

    // each thread: centroids tid and tid+256
    for (int cc = 0; cc < 2; cc++) {
        int c = tid + cc * 256;
        const float4* w = reinterpret_cast<const float4*>(cw + (size_t)c * HD);
        float acc[TT];
        #pragma unroll
        for (int tt = 0; tt < TT; tt++) acc[tt] = 0.f;
        for (int j = 0; j < HD / 4; j++) {
            float4 wv = w[j];
            #pragma unroll
            for (int tt = 0; tt < TT; tt++) {
                float4 hv = hsm[tt][j];
                acc[tt] += wv.x * hv.x + wv.y * hv.y + wv.z * hv.z + wv.w * hv.w;
            }
        }
        #pragma unroll
        for (int tt = 0; tt < TT; tt++) lg[tt][c] = acc[tt];
    }
    __syncthreads();

    // warp w does top-2 for token t0+w (ties -> smaller index, matching top_k)
    int warp = tid >> 5, lane = tid & 31;
    int t = t0 + warp;
    float bv = -__int_as_float(0x7f800000);  // -inf
    int   bi = 0x7FFFFFFF;
    for (int c = lane; c < NC; c += 32) {
        float v = lg[warp][c];
        if (v > bv || (v == bv && c < bi)) { bv = v; bi = c; }
    }
    #pragma unroll
    for (int o = 16; o; o >>= 1) {
        float ov = __shfl_xor_sync(0xFFFFFFFFu, bv, o);
        int   oi = __shfl_xor_sync(0xFFFFFFFFu, bi, o);
        if (ov > bv || (ov == bv && oi < bi)) { bv = ov; bi = oi; }
    }
    int i0 = bi;
    // second pass excluding i0
    bv = -__int_as_float(0x7f800000);
    bi = 0x7FFFFFFF;
    for (int c = lane; c < NC; c += 32) {
        if (c == i0) continue;
        float v = lg[warp][c];
        if (v > bv || (v == bv && c < bi)) { bv = v; bi = c; }
    }
    #pragma unroll
    for (int o = 16; o; o >>= 1) {
        float ov = __shfl_xor_sync(0xFFFFFFFFu, bv, o);
        int   oi = __shfl_xor_sync(0xFFFFFFFFu, bi, o);
        if (ov > bv || (ov == bv && oi < bi)) { bv = ov; bi = oi; }
    }
    int i1 = bi;

    if (lane == 0) {
        g_top2[t * 2 + 0] = i0;
        g_top2[t * 2 + 1] = i1;
        int p0 = atomicAdd(&g_count[i0], 1);
        g_list[i0 * NT + p0] = (t << 1);
        int p1 = atomicAdd(&g_count[i1], 1);
        g_list[i1 * NT + p1] = (t << 1) | 1;
    }
}

// ---------------------------------------------------------------------------
// K2: cluster-major candidate logits. One block per cluster; each touched
// cluster's 256 lm_head rows are read ONCE (for n<=8) and dotted against all
// tokens routed here (held in smem, chunks of 8). Row stays in registers
// across the token chunk. Tracks block-local min -> atomicMin.
// ---------------------------------------------------------------------------
__global__ void __launch_bounds__(256) k_gather(const float* __restrict__ hs,
                                                const float* __restrict__ W,
                                                const int* __restrict__ ordering) {
    int c = blockIdx.x;
    int n = g_count[c];
    if (n == 0) return;

    const int TCH = 8;
    __shared__ float4 hsm[TCH][HD / 4];  // 32 KB
    __shared__ int    meta[TCH];
    __shared__ unsigned s_min[8];

    int tid = threadIdx.x, warp = tid >> 5, lane = tid & 31;
    unsigned lmin = 0xFFFFFFFFu;

    for (int t0 = 0; t0 < n; t0 += TCH) {
        int ncur = min(TCH, n - t0);
        __syncthreads();
        for (int e = tid; e < ncur * (HD / 4); e += 256) {
            int tt = e >> 8, j = e & 255;
            int pk = g_list[c * NT + t0 + tt];
            hsm[tt][j] = reinterpret_cast<const float4*>(hs)[(size_t)(pk >> 1) * (HD / 4) + j];
        }
        if (tid < ncur) meta[tid] = g_list[c * NT + t0 + tid];
        __syncthreads();

        // 8 warps stride the 256 rows of this cluster
        for (int r = warp; r < VPC; r += 8) {
            int vocab = __ldg(&ordering[c * VPC + r]);
            const float4* wr = reinterpret_cast<const float4*>(W + (size_t)vocab * HD);
            float4 rv[8];
            #pragma unroll
            for (int q = 0; q < 8; q++) rv[q] = wr[lane + 32 * q];

            for (int e = 0; e < ncur; e++) {
                float p = 0.f;
                #pragma unroll
                for (int q = 0; q < 8; q++) {
                    float4 hv = hsm[e][lane + 32 * q];
                    p += rv[q].x * hv.x + rv[q].y * hv.y + rv[q].z * hv.z + rv[q].w * hv.w;
                }
                #pragma unroll
                for (int o = 16; o; o >>= 1) p += __shfl_xor_sync(0xFFFFFFFFu, p, o);
                if (lane == 0) {
                    int pk = meta[e];
                    int t = pk >> 1, k = pk & 1;
                    g_sel[(size_t)t * (TOPK * VPC) + k * VPC + r] = p;
                    unsigned key = enc_f(p);
                    if (key < lmin) lmin = key;
                }
            }
        }
    }

    // block-reduce min -> atomicMin
    #pragma unroll
    for (int o = 16; o; o >>= 1) {
        unsigned ov = __shfl_xor_sync(0xFFFFFFFFu, lmin, o);
        if (ov < lmin) lmin = ov;
    }
    if (lane == 0) s_min[warp] = lmin;
    __syncthreads();
    if (tid == 0) {
        unsigned m = s_min[0];
        #pragma unroll
        for (int w = 1; w < 8; w++) m = min(m, s_min[w]);
        atomicMin(&g_minkey, m);
    }
}

// ---------------------------------------------------------------------------
// K3: gather-style output fill (no scatter). Each thread writes one float4.
// t is constant per block (128 blocks per token) -> broadcast top2/mask via
// shared. out[t][v] = sel[t][k][inv[v]&255] if inv[v]>>8 in top2, else mask.
// ---------------------------------------------------------------------------
__global__ void __launch_bounds__(256) k_fill(float* __restrict__ out) {
    __shared__ int   s_c0, s_c1;
    __shared__ float s_mask;
    unsigned idx = blockIdx.x * 256u + threadIdx.x;  // float4 index, total NT*NV/4
    int t  = idx >> 15;        // NV/4 = 32768 float4 per token
    int v4 = idx & 32767;
    if (threadIdx.x == 0) {
        s_c0 = g_top2[t * 2 + 0];
        s_c1 = g_top2[t * 2 + 1];
        s_mask = dec_f(g_minkey) - 1.0f;
    }
    __syncthreads();
    int c0 = s_c0, c1 = s_c1;
    float maskv = s_mask;
    int4 iv = __ldg(&reinterpret_cast<const int4*>(g_inv)[v4]);
    const float* selt = g_sel + (size_t)t * (TOPK * VPC);

    float4 o;
    {
        int c = iv.x >> 8, s = iv.x & 255;
        o.x = (c == c0) ? __ldg(&selt[s]) : (c == c1) ? __ldg(&selt[VPC + s]) : maskv;
    }
    {
        int c = iv.y >> 8, s = iv.y & 255;
        o.y = (c == c0) ? __ldg(&selt[s]) : (c == c1) ? __ldg(&selt[VPC + s]) : maskv;
    }
    {
        int c = iv.z >> 8, s = iv.z & 255;
        o.z = (c == c0) ? __ldg(&selt[s]) : (c == c1) ? __ldg(&selt[VPC + s]) : maskv;
    }
    {
        int c = iv.w >> 8, s = iv.w & 255;
        o.w = (c == c0) ? __ldg(&selt[s]) : (c == c1) ? __ldg(&selt[VPC + s]) : maskv;
    }
    reinterpret_cast<float4*>(out)[idx] = o;
}

// ---------------------------------------------------------------------------
extern "C" void kernel_launch(void* const* d_in, const int* in_sizes, int n_in,
                              void* d_out, int out_size) {
    const float* hs = (const float*)d_in[0];  // [2,256,1024]
    const float* W  = (const float*)d_in[1];  // [131072,1024]
    const float* cw = (const float*)d_in[2];  // [512,1024]
    const int*   to = (const int*)d_in[3];    // [131072]
    float* out = (float*)d_out;               // [2,256,131072]

    k_init<<<NV / 256, 256>>>(to);
    k_route<<<NT / 8, 256>>>(hs, cw);
    k_gather<<<NC, 256>>>(hs, W, to);
    k_fill<<<(unsigned)((size_t)NT * NV / 4 / 256), 256>>>(out);
}

// round 3
// speedup vs baseline: 1.6170x; 1.6170x over previous
#include <cuda_runtime.h>
#include <cstdint>

// Problem constants (B=2, S=256, H=1024, V=131072, C=512, TOP_K=2)
#define NT   512      // B*S tokens
#define HD   1024     // hidden
#define NC   512      // centroids
#define NV   131072   // vocab
#define VPC  256      // vocab per centroid = NV/NC
#define TOPK 2
#define SPLIT 4       // row-split of each cluster in k_gather

// ---- scratch (no allocations allowed) ----
__device__ float    g_lg[NT * NC];           // routing logits [t][c]
__device__ int      g_top2[NT * TOPK];       // top-2 cluster ids per token
__device__ int      g_count[NC];             // tokens routed to each cluster
__device__ int      g_list[NC * NT];         // packed (token<<1)|k per cluster
__device__ float    g_sel[NT * TOPK * VPC];  // selected logits [t][k][r]
__device__ unsigned g_minkey;                // order-preserving-encoded global min

// order-preserving float<->uint mapping (monotone for unsigned compare)
__device__ __forceinline__ unsigned enc_f(float f) {
    unsigned u = __float_as_uint(f);
    return (u & 0x80000000u) ? ~u : (u | 0x80000000u);
}
__device__ __forceinline__ float dec_f(unsigned u) {
    return __uint_as_float((u & 0x80000000u) ? (u ^ 0x80000000u) : ~u);
}

// ---------------------------------------------------------------------------
// K0: zero counters, init min
// ---------------------------------------------------------------------------
__global__ void k_init() {
    int i = blockIdx.x * blockDim.x + threadIdx.x;
    if (i < NC) g_count[i] = 0;
    if (i == 0) g_minkey = 0xFFFFFFFFu;
}

// ---------------------------------------------------------------------------
// K1a: routing logits GEMM  g_lg[t][c] = <hs[t], cw[c]>
// 32x32 output tile per block, grid (NC/32, NT/32) = (16,16) = 256 blocks.
// Coalesced global loads staged through padded smem; thread computes 2x2.
// ---------------------------------------------------------------------------
#define KC 64
__global__ void __launch_bounds__(256) k_logits(const float* __restrict__ hs,
                                                const float* __restrict__ cw) {
    __shared__ float As[32][KC + 1];  // tokens   (padded: bank-conflict-free)
    __shared__ float Bs[32][KC + 1];  // centroids
    int bx = blockIdx.x;              // centroid tile
    int by = blockIdx.y;              // token tile
    int tid = threadIdx.x;
    int tx = tid & 15, ty = tid >> 4;

    float acc00 = 0.f, acc01 = 0.f, acc10 = 0.f, acc11 = 0.f;

    for (int kc = 0; kc < HD; kc += KC) {
        __syncthreads();
        #pragma unroll
        for (int l = tid; l < 512; l += 256) {
            int row = l >> 4, kq = (l & 15) << 2;
            float4 a = *reinterpret_cast<const float4*>(
                &hs[(size_t)(by * 32 + row) * HD + kc + kq]);
            As[row][kq] = a.x; As[row][kq + 1] = a.y;
            As[row][kq + 2] = a.z; As[row][kq + 3] = a.w;
            float4 b = *reinterpret_cast<const float4*>(
                &cw[(size_t)(bx * 32 + row) * HD + kc + kq]);
            Bs[row][kq] = b.x; Bs[row][kq + 1] = b.y;
            Bs[row][kq + 2] = b.z; Bs[row][kq + 3] = b.w;
        }
        __syncthreads();
        #pragma unroll
        for (int kk = 0; kk < KC; kk++) {
            float a0 = As[ty * 2][kk],     a1 = As[ty * 2 + 1][kk];
            float b0 = Bs[tx * 2][kk],     b1 = Bs[tx * 2 + 1][kk];
            acc00 += b0 * a0; acc01 += b0 * a1;
            acc10 += b1 * a0; acc11 += b1 * a1;
        }
    }
    int t = by * 32 + ty * 2, c = bx * 32 + tx * 2;
    g_lg[(size_t)t * NC + c]            = acc00;
    g_lg[(size_t)t * NC + c + 1]        = acc10;
    g_lg[(size_t)(t + 1) * NC + c]      = acc01;
    g_lg[(size_t)(t + 1) * NC + c + 1]  = acc11;
}

// ---------------------------------------------------------------------------
// K1b: top-2 per token from g_lg + build per-cluster token lists.
// warp per token; 64 blocks x 8 warps.
// ---------------------------------------------------------------------------
__global__ void __launch_bounds__(256) k_top2() {
    int warp = threadIdx.x >> 5, lane = threadIdx.x & 31;
    int t = blockIdx.x * 8 + warp;
    const float* row = g_lg + (size_t)t * NC;

    float bv = -__int_as_float(0x7f800000);
    int   bi = 0x7FFFFFFF;
    for (int c = lane; c < NC; c += 32) {
        float v = row[c];
        if (v > bv || (v == bv && c < bi)) { bv = v; bi = c; }
    }
    #pragma unroll
    for (int o = 16; o; o >>= 1) {
        float ov = __shfl_xor_sync(0xFFFFFFFFu, bv, o);
        int   oi = __shfl_xor_sync(0xFFFFFFFFu, bi, o);
        if (ov > bv || (ov == bv && oi < bi)) { bv = ov; bi = oi; }
    }
    int i0 = bi;
    bv = -__int_as_float(0x7f800000);
    bi = 0x7FFFFFFF;
    for (int c = lane; c < NC; c += 32) {
        if (c == i0) continue;
        float v = row[c];
        if (v > bv || (v == bv && c < bi)) { bv = v; bi = c; }
    }
    #pragma unroll
    for (int o = 16; o; o >>= 1) {
        float ov = __shfl_xor_sync(0xFFFFFFFFu, bv, o);
        int   oi = __shfl_xor_sync(0xFFFFFFFFu, bi, o);
        if (ov > bv || (ov == bv && oi < bi)) { bv = ov; bi = oi; }
    }
    int i1 = bi;

    if (lane == 0) {
        g_top2[t * 2 + 0] = i0;
        g_top2[t * 2 + 1] = i1;
        int p0 = atomicAdd(&g_count[i0], 1);
        g_list[i0 * NT + p0] = (t << 1);
        int p1 = atomicAdd(&g_count[i1], 1);
        g_list[i1 * NT + p1] = (t << 1) | 1;
    }
}

// ---------------------------------------------------------------------------
// K2: cluster-major candidate logits. Grid (NC, SPLIT): block handles 64 rows
// of cluster c. Rows read once, dotted against all routed tokens (smem).
// Tracks block-local min -> atomicMin.
// ---------------------------------------------------------------------------
__global__ void __launch_bounds__(256) k_gather(const float* __restrict__ hs,
                                                const float* __restrict__ W,
                                                const int* __restrict__ ordering) {
    int c = blockIdx.x;
    int n = g_count[c];
    if (n == 0) return;
    int r0 = blockIdx.y * (VPC / SPLIT);

    const int TCH = 8;
    __shared__ float4 hsm[TCH][HD / 4];  // 32 KB
    __shared__ int    meta[TCH];
    __shared__ unsigned s_min[8];

    int tid = threadIdx.x, warp = tid >> 5, lane = tid & 31;
    unsigned lmin = 0xFFFFFFFFu;

    for (int t0 = 0; t0 < n; t0 += TCH) {
        int ncur = min(TCH, n - t0);
        __syncthreads();
        for (int e = tid; e < ncur * (HD / 4); e += 256) {
            int tt = e >> 8, j = e & 255;
            int pk = g_list[c * NT + t0 + tt];
            hsm[tt][j] = reinterpret_cast<const float4*>(hs)[(size_t)(pk >> 1) * (HD / 4) + j];
        }
        if (tid < ncur) meta[tid] = g_list[c * NT + t0 + tid];
        __syncthreads();

        // 8 warps stride the 64 rows of this block's slice
        for (int r = r0 + warp; r < r0 + VPC / SPLIT; r += 8) {
            int vocab = __ldg(&ordering[c * VPC + r]);
            const float4* wr = reinterpret_cast<const float4*>(W + (size_t)vocab * HD);
            float4 rv[8];
            #pragma unroll
            for (int q = 0; q < 8; q++) rv[q] = wr[lane + 32 * q];

            for (int e = 0; e < ncur; e++) {
                float p = 0.f;
                #pragma unroll
                for (int q = 0; q < 8; q++) {
                    float4 hv = hsm[e][lane + 32 * q];
                    p += rv[q].x * hv.x + rv[q].y * hv.y + rv[q].z * hv.z + rv[q].w * hv.w;
                }
                #pragma unroll
                for (int o = 16; o; o >>= 1) p += __shfl_xor_sync(0xFFFFFFFFu, p, o);
                if (lane == 0) {
                    int pk = meta[e];
                    int t = pk >> 1, k = pk & 1;
                    g_sel[(size_t)t * (TOPK * VPC) + k * VPC + r] = p;
                    unsigned key = enc_f(p);
                    if (key < lmin) lmin = key;
                }
            }
        }
    }

    #pragma unroll
    for (int o = 16; o; o >>= 1) {
        unsigned ov = __shfl_xor_sync(0xFFFFFFFFu, lmin, o);
        if (ov < lmin) lmin = ov;
    }
    if (lane == 0) s_min[warp] = lmin;
    __syncthreads();
    if (tid == 0) {
        unsigned m = s_min[0];
        #pragma unroll
        for (int w = 1; w < 8; w++) m = min(m, s_min[w]);
        atomicMin(&g_minkey, m);
    }
}

// ---------------------------------------------------------------------------
// K3a: pure streaming mask fill — no reads except minkey (broadcast via smem).
// Each block writes 1024 consecutive float4 (16 KB), fully coalesced STG.128.
// ---------------------------------------------------------------------------
__global__ void __launch_bounds__(256) k_fillmask(float4* __restrict__ out) {
    __shared__ float s_mask;
    if (threadIdx.x == 0) s_mask = dec_f(g_minkey) - 1.0f;
    __syncthreads();
    float m = s_mask;
    float4 mv = make_float4(m, m, m, m);
    size_t base = (size_t)blockIdx.x * 1024 + threadIdx.x;
    #pragma unroll
    for (int j = 0; j < 4; j++) out[base + j * 256] = mv;
}

// ---------------------------------------------------------------------------
// K3b: scatter candidate logits over the mask. One block per token,
// 512 threads = (k,r). With identity ordering the stores are two coalesced
// 1 KB runs per (t,k); for general permutations still only ~1 MB scattered.
// ---------------------------------------------------------------------------
__global__ void __launch_bounds__(512) k_scatter(float* __restrict__ out,
                                                 const int* __restrict__ ordering) {
    int t = blockIdx.x;
    int tid = threadIdx.x;          // = k*256 + r
    int k = tid >> 8, r = tid & 255;
    int c = g_top2[t * 2 + k];
    int v = __ldg(&ordering[c * VPC + r]);
    out[(size_t)t * NV + v] = g_sel[(size_t)t * (TOPK * VPC) + tid];
}

// ---------------------------------------------------------------------------
extern "C" void kernel_launch(void* const* d_in, const int* in_sizes, int n_in,
                              void* d_out, int out_size) {
    const float* hs = (const float*)d_in[0];  // [2,256,1024]
    const float* W  = (const float*)d_in[1];  // [131072,1024]
    const float* cw = (const float*)d_in[2];  // [512,1024]
    const int*   to = (const int*)d_in[3];    // [131072]
    float* out = (float*)d_out;               // [2,256,131072]

    k_init<<<2, 256>>>();
    k_logits<<<dim3(NC / 32, NT / 32), 256>>>(hs, cw);
    k_top2<<<NT / 8, 256>>>();
    k_gather<<<dim3(NC, SPLIT), 256>>>(hs, W, to);
    k_fillmask<<<(unsigned)((size_t)NT * NV / 4 / 1024), 256>>>((float4*)out);
    k_scatter<<<NT, 512>>>(out, to);
}